// round 10
// baseline (speedup 1.0000x reference)
#include <cuda_runtime.h>
#include <math.h>

#define BB 16
#define HH 96
#define WW 96
#define CC 128
#define HWSZ 9216           // H*W
#define NPIX 147456         // B*H*W
#define LN_EPS 1e-3f

// ---------------- scratch (device globals; no allocation allowed) -----------
__device__ float g_q[NPIX * CC];       // NHWC
__device__ float g_ctx[NPIX * CC];     // NCHW  (b,c,h,w)
__device__ float g_ctxall[NPIX * CC];  // NCHW
__device__ float g_gates[NPIX * 4];    // NHWC4
__device__ float g_xout[NPIX * CC];    // NHWC
__device__ float g_pool[BB * CC];
__device__ float g_cg[BB * CC];        // gelu(mean ctx3) per (b, c)

__device__ __forceinline__ float gelu_exact(float v) {
    return 0.5f * v * (1.0f + erff(v * 0.70710678118654752f));
}

// ---------------- zero pool accumulator -------------------------------------
__global__ void zero_pool_kernel() {
    int i = blockIdx.x * blockDim.x + threadIdx.x;
    if (i < BB * CC) g_pool[i] = 0.0f;
}

// ---------------- GEMM1: y = x @ Wf[:, :256] + bf ---------------------------
// BM=64, BN=128, BK=16, 256 threads, TM=4, TN=8.
// blockIdx.x == 0 -> q (NHWC), blockIdx.x == 1 -> ctx (NCHW).
__global__ __launch_bounds__(256) void gemm1_kernel(
    const float* __restrict__ x, const float* __restrict__ Wf,
    const float* __restrict__ bf)
{
    __shared__ float As[16][64];
    __shared__ float Bs[16][128];
    const int tid = threadIdx.x;
    const int tx = tid & 15, ty = tid >> 4;
    const int row0 = blockIdx.y * 64;
    const int n0 = blockIdx.x * 128;  // column offset into Wf (0 or 128)

    float acc[4][8];
#pragma unroll
    for (int i = 0; i < 4; i++)
#pragma unroll
        for (int j = 0; j < 8; j++) acc[i][j] = 0.0f;

    const int la_m = tid >> 2;         // 0..63
    const int la_k = (tid & 3) * 4;    // 0,4,8,12
    const int lb_k = tid >> 5;         // 0..7
    const int lb_n = (tid & 31) * 4;   // 0..124

    for (int k0 = 0; k0 < 128; k0 += 16) {
        float4 av = *(const float4*)(x + (size_t)(row0 + la_m) * CC + k0 + la_k);
        As[la_k + 0][la_m] = av.x;
        As[la_k + 1][la_m] = av.y;
        As[la_k + 2][la_m] = av.z;
        As[la_k + 3][la_m] = av.w;
#pragma unroll
        for (int pass = 0; pass < 2; pass++) {
            int kk = lb_k + pass * 8;
            float4 bv = *(const float4*)(Wf + (size_t)(k0 + kk) * 260 + n0 + lb_n);
            *(float4*)&Bs[kk][lb_n] = bv;
        }
        __syncthreads();
#pragma unroll
        for (int k = 0; k < 16; k++) {
            float4 a = *(const float4*)&As[k][ty * 4];
            float4 b0 = *(const float4*)&Bs[k][tx * 8];
            float4 b1 = *(const float4*)&Bs[k][tx * 8 + 4];
            float am[4] = {a.x, a.y, a.z, a.w};
            float bn[8] = {b0.x, b0.y, b0.z, b0.w, b1.x, b1.y, b1.z, b1.w};
#pragma unroll
            for (int i = 0; i < 4; i++)
#pragma unroll
                for (int j = 0; j < 8; j++) acc[i][j] = fmaf(am[i], bn[j], acc[i][j]);
        }
        __syncthreads();
    }

    const int colb = tx * 8;
    if (blockIdx.x == 0) {
        // q path: NHWC, bias bf[col]
        float bv[8];
#pragma unroll
        for (int j = 0; j < 8; j++) bv[j] = __ldg(bf + colb + j);
#pragma unroll
        for (int i = 0; i < 4; i++) {
            int r = row0 + ty * 4 + i;
            float4 o0 = {acc[i][0] + bv[0], acc[i][1] + bv[1], acc[i][2] + bv[2], acc[i][3] + bv[3]};
            float4 o1 = {acc[i][4] + bv[4], acc[i][5] + bv[5], acc[i][6] + bv[6], acc[i][7] + bv[7]};
            *(float4*)(g_q + (size_t)r * CC + colb) = o0;
            *(float4*)(g_q + (size_t)r * CC + colb + 4) = o1;
        }
    } else {
        // ctx path: NCHW, bias bf[128+col]
        const int b = row0 / HWSZ;
        const int p0 = row0 % HWSZ;
#pragma unroll
        for (int j = 0; j < 8; j++) {
            int col = colb + j;
            float bias = __ldg(bf + 128 + col);
            float4 v = {acc[0][j] + bias, acc[1][j] + bias, acc[2][j] + bias, acc[3][j] + bias};
            *(float4*)(g_ctx + (size_t)(b * CC + col) * HWSZ + p0 + ty * 4) = v;
        }
    }
}

// ---------------- gates: x @ Wf[:, 256:260] + bf[256:260] -------------------
// one warp per pixel, 8 pixels per 256-thread block
__global__ __launch_bounds__(256) void gates_kernel(
    const float* __restrict__ x, const float* __restrict__ Wf,
    const float* __restrict__ bf)
{
    const int warp = threadIdx.x >> 5, lane = threadIdx.x & 31;
    const int n = blockIdx.x * 8 + warp;
    float4 xv = *(const float4*)(x + (size_t)n * CC + lane * 4);
    float s0 = 0.f, s1 = 0.f, s2 = 0.f, s3 = 0.f;
    float xa[4] = {xv.x, xv.y, xv.z, xv.w};
#pragma unroll
    for (int t = 0; t < 4; t++) {
        int k = lane * 4 + t;
        const float* wrow = Wf + (size_t)k * 260 + 256;
        s0 = fmaf(xa[t], __ldg(wrow + 0), s0);
        s1 = fmaf(xa[t], __ldg(wrow + 1), s1);
        s2 = fmaf(xa[t], __ldg(wrow + 2), s2);
        s3 = fmaf(xa[t], __ldg(wrow + 3), s3);
    }
#pragma unroll
    for (int off = 16; off; off >>= 1) {
        s0 += __shfl_xor_sync(0xffffffffu, s0, off);
        s1 += __shfl_xor_sync(0xffffffffu, s1, off);
        s2 += __shfl_xor_sync(0xffffffffu, s2, off);
        s3 += __shfl_xor_sync(0xffffffffu, s3, off);
    }
    if (lane == 0) {
        float4 g = {s0 + __ldg(bf + 256), s1 + __ldg(bf + 257),
                    s2 + __ldg(bf + 258), s3 + __ldg(bf + 259)};
        *(float4*)(g_gates + (size_t)n * 4) = g;
    }
}

// ---------------- fused 3-level depthwise conv + gated accumulate -----------
// one block per (tile, channel, batch); 32x32 output tile, halo 6.
// IMPORTANT: halo values of ctx1/ctx2 that lie OUTSIDE the image must be zero
// (reference zero-pads each conv's input at the image boundary), not the
// "virtual" conv output computed from the zero-extended previous level.
__global__ __launch_bounds__(256) void conv_kernel(
    const float* __restrict__ kw0, const float* __restrict__ kw1,
    const float* __restrict__ kw2)
{
    __shared__ float buf0[44 * 44];
    __shared__ float buf1[42 * 42];
    __shared__ float buf2[38 * 38];
    __shared__ float wts[83];
    __shared__ float red[256];

    const int tid = threadIdx.x;
    const int tile = blockIdx.x;
    const int ty0 = (tile / 3) * 32, tx0 = (tile % 3) * 32;
    const int c = blockIdx.y, b = blockIdx.z;
    const float* src = g_ctx + (size_t)(b * CC + c) * HWSZ;

    if (tid < 9)       wts[tid] = __ldg(kw0 + tid * CC + c);
    else if (tid < 34) wts[tid] = __ldg(kw1 + (tid - 9) * CC + c);
    else if (tid < 83) wts[tid] = __ldg(kw2 + (tid - 34) * CC + c);

    for (int idx = tid; idx < 44 * 44; idx += 256) {
        int ly = idx / 44, lx = idx % 44;
        int gy = ty0 - 6 + ly, gx = tx0 - 6 + lx;
        float v = 0.0f;
        if (gy >= 0 && gy < HH && gx >= 0 && gx < WW) v = src[gy * WW + gx];
        buf0[idx] = v;
    }
    __syncthreads();

    // level 0: 3x3 -> ctx1 at global (ty0-5+oy, tx0-5+ox); zero outside image
    for (int idx = tid; idx < 42 * 42; idx += 256) {
        int oy = idx / 42, ox = idx % 42;
        int gy = ty0 - 5 + oy, gx = tx0 - 5 + ox;
        float s = 0.0f;
#pragma unroll
        for (int i = 0; i < 3; i++)
#pragma unroll
            for (int j = 0; j < 3; j++)
                s = fmaf(buf0[(oy + i) * 44 + ox + j], wts[i * 3 + j], s);
        bool inimg = (gy >= 0) & (gy < HH) & (gx >= 0) & (gx < WW);
        buf1[idx] = inimg ? gelu_exact(s) : 0.0f;
    }
    __syncthreads();

    // level 1: 5x5 -> ctx2 at global (ty0-3+oy, tx0-3+ox); zero outside image
    for (int idx = tid; idx < 38 * 38; idx += 256) {
        int oy = idx / 38, ox = idx % 38;
        int gy = ty0 - 3 + oy, gx = tx0 - 3 + ox;
        float s = 0.0f;
#pragma unroll
        for (int i = 0; i < 5; i++)
#pragma unroll
            for (int j = 0; j < 5; j++)
                s = fmaf(buf1[(oy + i) * 42 + ox + j], wts[9 + i * 5 + j], s);
        bool inimg = (gy >= 0) & (gy < HH) & (gx >= 0) & (gx < WW);
        buf2[idx] = inimg ? gelu_exact(s) : 0.0f;
    }
    __syncthreads();

    // level 2: 7x7 + gated accumulation + pooled sum of final ctx
    float psum = 0.0f;
    for (int idx = tid; idx < 32 * 32; idx += 256) {
        int oy = idx / 32, ox = idx % 32;
        float s = 0.0f;
#pragma unroll
        for (int i = 0; i < 7; i++)
#pragma unroll
            for (int j = 0; j < 7; j++)
                s = fmaf(buf2[(oy + i) * 38 + ox + j], wts[34 + i * 7 + j], s);
        float c3 = gelu_exact(s);
        psum += c3;
        int gy = ty0 + oy, gx = tx0 + ox;
        int n = b * HWSZ + gy * WW + gx;
        float4 g = *(const float4*)(g_gates + (size_t)n * 4);
        float val = buf1[(oy + 5) * 42 + (ox + 5)] * g.x
                  + buf2[(oy + 3) * 38 + (ox + 3)] * g.y
                  + c3 * g.z;
        g_ctxall[(size_t)(b * CC + c) * HWSZ + gy * WW + gx] = val;
    }

    red[tid] = psum;
    __syncthreads();
#pragma unroll
    for (int s = 128; s > 0; s >>= 1) {
        if (tid < s) red[tid] += red[tid + s];
        __syncthreads();
    }
    if (tid == 0) atomicAdd(&g_pool[b * CC + c], red[0]);
}

// ---------------- pooled-branch: cg = gelu(mean ctx3) -----------------------
__global__ void poolm_kernel() {
    const int b = blockIdx.x, t = threadIdx.x;
    g_cg[b * CC + t] = gelu_exact(g_pool[b * CC + t] * (1.0f / (float)HWSZ));
}

// ---------------- GEMM2: modulator + q-mult + LayerNorm ---------------------
// A[pix, c] = ctx_all + g3[pix] * cg[c], B = Wh. BM=64, BN=128, BK=16.
__global__ __launch_bounds__(256) void gemm2_kernel(
    const float* __restrict__ Wh, const float* __restrict__ bh,
    const float* __restrict__ gamma, const float* __restrict__ beta)
{
    __shared__ float As[16][64];
    __shared__ float Bs[16][128];
    __shared__ float sg3[64];
    __shared__ float scg[CC];
    __shared__ float redS[64][16];
    __shared__ float redQ[64][16];
    __shared__ float smu[64], srs[64];

    const int tid = threadIdx.x;
    const int tx = tid & 15, ty = tid >> 4;
    const int row0 = blockIdx.x * 64;
    const int b = row0 / HWSZ;
    const int p0 = row0 % HWSZ;

    if (tid < 64) sg3[tid] = g_gates[(size_t)(row0 + tid) * 4 + 3];
    else if (tid < 192) scg[tid - 64] = g_cg[b * CC + (tid - 64)];
    __syncthreads();

    float acc[4][8];
#pragma unroll
    for (int i = 0; i < 4; i++)
#pragma unroll
        for (int j = 0; j < 8; j++) acc[i][j] = 0.0f;

    const int la_k = tid >> 4;          // 0..15
    const int la_m = (tid & 15) * 4;    // 0..60
    const int lb_k = tid >> 5;          // 0..7
    const int lb_n = (tid & 31) * 4;

    for (int k0 = 0; k0 < 128; k0 += 16) {
        float4 av = *(const float4*)(g_ctxall + (size_t)(b * CC + k0 + la_k) * HWSZ + p0 + la_m);
        float cgk = scg[k0 + la_k];
        As[la_k][la_m + 0] = av.x + sg3[la_m + 0] * cgk;
        As[la_k][la_m + 1] = av.y + sg3[la_m + 1] * cgk;
        As[la_k][la_m + 2] = av.z + sg3[la_m + 2] * cgk;
        As[la_k][la_m + 3] = av.w + sg3[la_m + 3] * cgk;
#pragma unroll
        for (int pass = 0; pass < 2; pass++) {
            int kk = lb_k + pass * 8;
            *(float4*)&Bs[kk][lb_n] = *(const float4*)(Wh + (size_t)(k0 + kk) * CC + lb_n);
        }
        __syncthreads();
#pragma unroll
        for (int k = 0; k < 16; k++) {
            float4 a = *(const float4*)&As[k][ty * 4];
            float4 b0 = *(const float4*)&Bs[k][tx * 8];
            float4 b1 = *(const float4*)&Bs[k][tx * 8 + 4];
            float am[4] = {a.x, a.y, a.z, a.w};
            float bn[8] = {b0.x, b0.y, b0.z, b0.w, b1.x, b1.y, b1.z, b1.w};
#pragma unroll
            for (int i = 0; i < 4; i++)
#pragma unroll
                for (int j = 0; j < 8; j++) acc[i][j] = fmaf(am[i], bn[j], acc[i][j]);
        }
        __syncthreads();
    }

    const int colb = tx * 8;
    float bhv[8];
#pragma unroll
    for (int j = 0; j < 8; j++) bhv[j] = __ldg(bh + colb + j);

    float xo[4][8];
#pragma unroll
    for (int i = 0; i < 4; i++) {
        int r = row0 + ty * 4 + i;
        float4 q0 = *(const float4*)(g_q + (size_t)r * CC + colb);
        float4 q1 = *(const float4*)(g_q + (size_t)r * CC + colb + 4);
        float qa[8] = {q0.x, q0.y, q0.z, q0.w, q1.x, q1.y, q1.z, q1.w};
        float ps = 0.0f, pq = 0.0f;
#pragma unroll
        for (int j = 0; j < 8; j++) {
            float mod = acc[i][j] + bhv[j];
            float v = qa[j] * mod;
            xo[i][j] = v;
            ps += v;
            pq = fmaf(v, v, pq);
        }
        redS[ty * 4 + i][tx] = ps;
        redQ[ty * 4 + i][tx] = pq;
    }
    __syncthreads();
    if (tid < 64) {
        float s = 0.0f, sq = 0.0f;
#pragma unroll
        for (int t = 0; t < 16; t++) { s += redS[tid][t]; sq += redQ[tid][t]; }
        float mu = s * (1.0f / CC);
        float var = sq * (1.0f / CC) - mu * mu;
        smu[tid] = mu;
        srs[tid] = rsqrtf(var + LN_EPS);
    }
    __syncthreads();

    float gmv[8], bev[8];
#pragma unroll
    for (int j = 0; j < 8; j++) {
        gmv[j] = __ldg(gamma + colb + j);
        bev[j] = __ldg(beta + colb + j);
    }
#pragma unroll
    for (int i = 0; i < 4; i++) {
        int lr = ty * 4 + i;
        int r = row0 + lr;
        float mu = smu[lr], rs = srs[lr];
        float o[8];
#pragma unroll
        for (int j = 0; j < 8; j++) o[j] = fmaf((xo[i][j] - mu) * rs, gmv[j], bev[j]);
        *(float4*)(g_xout + (size_t)r * CC + colb) = make_float4(o[0], o[1], o[2], o[3]);
        *(float4*)(g_xout + (size_t)r * CC + colb + 4) = make_float4(o[4], o[5], o[6], o[7]);
    }
}

// ---------------- GEMM3: out = xout @ Wp + bp -------------------------------
__global__ __launch_bounds__(256) void gemm3_kernel(
    const float* __restrict__ Wp, const float* __restrict__ bp,
    float* __restrict__ out)
{
    __shared__ float As[16][64];
    __shared__ float Bs[16][128];
    const int tid = threadIdx.x;
    const int tx = tid & 15, ty = tid >> 4;
    const int row0 = blockIdx.x * 64;

    float acc[4][8];
#pragma unroll
    for (int i = 0; i < 4; i++)
#pragma unroll
        for (int j = 0; j < 8; j++) acc[i][j] = 0.0f;

    const int la_m = tid >> 2;
    const int la_k = (tid & 3) * 4;
    const int lb_k = tid >> 5;
    const int lb_n = (tid & 31) * 4;

    for (int k0 = 0; k0 < 128; k0 += 16) {
        float4 av = *(const float4*)(g_xout + (size_t)(row0 + la_m) * CC + k0 + la_k);
        As[la_k + 0][la_m] = av.x;
        As[la_k + 1][la_m] = av.y;
        As[la_k + 2][la_m] = av.z;
        As[la_k + 3][la_m] = av.w;
#pragma unroll
        for (int pass = 0; pass < 2; pass++) {
            int kk = lb_k + pass * 8;
            *(float4*)&Bs[kk][lb_n] = *(const float4*)(Wp + (size_t)(k0 + kk) * CC + lb_n);
        }
        __syncthreads();
#pragma unroll
        for (int k = 0; k < 16; k++) {
            float4 a = *(const float4*)&As[k][ty * 4];
            float4 b0 = *(const float4*)&Bs[k][tx * 8];
            float4 b1 = *(const float4*)&Bs[k][tx * 8 + 4];
            float am[4] = {a.x, a.y, a.z, a.w};
            float bn[8] = {b0.x, b0.y, b0.z, b0.w, b1.x, b1.y, b1.z, b1.w};
#pragma unroll
            for (int i = 0; i < 4; i++)
#pragma unroll
                for (int j = 0; j < 8; j++) acc[i][j] = fmaf(am[i], bn[j], acc[i][j]);
        }
        __syncthreads();
    }

    const int colb = tx * 8;
    float bv[8];
#pragma unroll
    for (int j = 0; j < 8; j++) bv[j] = __ldg(bp + colb + j);
#pragma unroll
    for (int i = 0; i < 4; i++) {
        int r = row0 + ty * 4 + i;
        float4 o0 = {acc[i][0] + bv[0], acc[i][1] + bv[1], acc[i][2] + bv[2], acc[i][3] + bv[3]};
        float4 o1 = {acc[i][4] + bv[4], acc[i][5] + bv[5], acc[i][6] + bv[6], acc[i][7] + bv[7]};
        *(float4*)(out + (size_t)r * CC + colb) = o0;
        *(float4*)(out + (size_t)r * CC + colb + 4) = o1;
    }
}

// ---------------- launcher ---------------------------------------------------
extern "C" void kernel_launch(void* const* d_in, const int* in_sizes, int n_in,
                              void* d_out, int out_size)
{
    const float *x = 0, *Wf = 0, *bf = 0, *Wh = 0, *bh = 0, *gamma = 0,
                *beta = 0, *Wp = 0, *bp = 0, *k0 = 0, *k1 = 0, *k2 = 0;
    int n16384 = 0, n128 = 0;
    for (int i = 0; i < n_in; i++) {
        const float* p = (const float*)d_in[i];
        switch (in_sizes[i]) {
            case 18874368: x = p; break;
            case 33280:    Wf = p; break;
            case 260:      bf = p; break;
            case 16384:    if (n16384++ == 0) Wh = p; else Wp = p; break;
            case 128:
                if (n128 == 0) bh = p;
                else if (n128 == 1) gamma = p;
                else if (n128 == 2) beta = p;
                else bp = p;
                n128++;
                break;
            case 1152:     k0 = p; break;
            case 3200:     k1 = p; break;
            case 6272:     k2 = p; break;
            default: break;
        }
    }
    float* out = (float*)d_out;

    zero_pool_kernel<<<8, 256>>>();
    gemm1_kernel<<<dim3(2, NPIX / 64), 256>>>(x, Wf, bf);
    gates_kernel<<<NPIX / 8, 256>>>(x, Wf, bf);
    conv_kernel<<<dim3(9, CC, BB), 256>>>(k0, k1, k2);
    poolm_kernel<<<BB, CC>>>();
    gemm2_kernel<<<NPIX / 64, 256>>>(Wh, bh, gamma, beta);
    gemm3_kernel<<<NPIX / 64, 256>>>(Wp, bp, out);
    (void)out_size;
}

// round 12
// speedup vs baseline: 2.2869x; 2.2869x over previous
#include <cuda_runtime.h>
#include <math.h>
#include <stdint.h>

#define BB 16
#define HH 96
#define WW 96
#define CC 128
#define HWSZ 9216
#define NPIX 147456
#define LN_EPS 1e-3f
#define AST 20
#define BST 136

__device__ float g_q[NPIX*CC];
__device__ float g_ctx[NPIX*CC];
__device__ float g_ctxall[NPIX*CC];
__device__ float g_gates[NPIX*4];
__device__ float g_xout[NPIX*CC];
__device__ float g_pool[BB*CC];
__device__ float g_cg[BB*CC];

__device__ __forceinline__ float gelu_exact(float v){return 0.5f*v*(1.0f+erff(v*0.70710678118654752f));}
__device__ __forceinline__ float to_tf32(float x){float r;asm("cvt.rna.tf32.f32 %0, %1;":"=f"(r):"f"(x));return r;}
__device__ __forceinline__ void split4(float4 v,float4* h,float4* l){
  float h0=to_tf32(v.x),h1=to_tf32(v.y),h2=to_tf32(v.z),h3=to_tf32(v.w);
  *h=make_float4(h0,h1,h2,h3);
  *l=make_float4(to_tf32(v.x-h0),to_tf32(v.y-h1),to_tf32(v.z-h2),to_tf32(v.w-h3));
}
__device__ __forceinline__ void mma8(float* c,uint32_t a0,uint32_t a1,uint32_t a2,uint32_t a3,uint32_t b0,uint32_t b1){
  asm volatile("mma.sync.aligned.m16n8k8.row.col.f32.tf32.tf32.f32 {%0,%1,%2,%3},{%4,%5,%6,%7},{%8,%9},{%0,%1,%2,%3};"
    :"+f"(c[0]),"+f"(c[1]),"+f"(c[2]),"+f"(c[3]):"r"(a0),"r"(a1),"r"(a2),"r"(a3),"r"(b0),"r"(b1));
}

__global__ void zero_pool_kernel(){
  int i=blockIdx.x*blockDim.x+threadIdx.x;
  if(i<BB*CC) g_pool[i]=0.0f;
}

// ============ tensor-core GEMM (3xTF32): C = A[row0:+128] @ W[:,n0:+128] + bias
// A==nullptr -> read from g_xout (device symbol must not be passed from host!).
// ctx_en: blockIdx.x==1 writes NCHW to g_ctx; else NHWC to dq (or g_q if dq==0).
__global__ __launch_bounds__(256) void gemmA_kernel(
  const float* __restrict__ A,const float* __restrict__ W,int ldw,
  const float* __restrict__ bias,float* __restrict__ dq,int ctx_en)
{
  __shared__ float AsH[128*AST],AsL[128*AST],BsH[16*BST],BsL[16*BST];
  const int tid=threadIdx.x,lane=tid&31,w=tid>>5;
  const int wm=(w&3)*32,wn=(w>>2)*64,gid=lane>>2,tig=lane&3;
  const int row0=blockIdx.y*128,n0=blockIdx.x*128;
  const float* Ap=A?A:(const float*)g_xout;
  const float* bi=bias+n0;
  float acc[2][8][4];
#pragma unroll
  for(int mi=0;mi<2;mi++)
#pragma unroll
    for(int ni=0;ni<8;ni++)
#pragma unroll
      for(int r=0;r<4;r++) acc[mi][ni][r]=0.0f;

  for(int kc=0;kc<128;kc+=16){
#pragma unroll
    for(int it=0;it<2;it++){
      int f=tid+256*it,m=f>>2,kq=(f&3)*4;
      float4 h,l,v=*(const float4*)(Ap+(size_t)(row0+m)*CC+kc+kq);
      split4(v,&h,&l);
      *(float4*)&AsH[m*AST+kq]=h; *(float4*)&AsL[m*AST+kq]=l;
    }
#pragma unroll
    for(int it=0;it<2;it++){
      int f=tid+256*it,k=f>>5,nq=(f&31)*4;
      float4 h,l,v=*(const float4*)(W+(size_t)(kc+k)*ldw+n0+nq);
      split4(v,&h,&l);
      *(float4*)&BsH[k*BST+nq]=h; *(float4*)&BsL[k*BST+nq]=l;
    }
    __syncthreads();
#pragma unroll
    for(int s=0;s<2;s++){
      int kb=s*8;
      uint32_t aH[2][4],aL[2][4];
#pragma unroll
      for(int mi=0;mi<2;mi++){
        int m0=wm+mi*16+gid;
        aH[mi][0]=__float_as_uint(AsH[m0*AST+kb+tig]);
        aH[mi][1]=__float_as_uint(AsH[(m0+8)*AST+kb+tig]);
        aH[mi][2]=__float_as_uint(AsH[m0*AST+kb+tig+4]);
        aH[mi][3]=__float_as_uint(AsH[(m0+8)*AST+kb+tig+4]);
        aL[mi][0]=__float_as_uint(AsL[m0*AST+kb+tig]);
        aL[mi][1]=__float_as_uint(AsL[(m0+8)*AST+kb+tig]);
        aL[mi][2]=__float_as_uint(AsL[m0*AST+kb+tig+4]);
        aL[mi][3]=__float_as_uint(AsL[(m0+8)*AST+kb+tig+4]);
      }
#pragma unroll
      for(int ni=0;ni<8;ni++){
        int nc=wn+ni*8+gid;
        uint32_t bH0=__float_as_uint(BsH[(kb+tig)*BST+nc]);
        uint32_t bH1=__float_as_uint(BsH[(kb+tig+4)*BST+nc]);
        uint32_t bL0=__float_as_uint(BsL[(kb+tig)*BST+nc]);
        uint32_t bL1=__float_as_uint(BsL[(kb+tig+4)*BST+nc]);
#pragma unroll
        for(int mi=0;mi<2;mi++){
          mma8(acc[mi][ni],aH[mi][0],aH[mi][1],aH[mi][2],aH[mi][3],bH0,bH1);
          mma8(acc[mi][ni],aH[mi][0],aH[mi][1],aH[mi][2],aH[mi][3],bL0,bL1);
          mma8(acc[mi][ni],aL[mi][0],aL[mi][1],aL[mi][2],aL[mi][3],bH0,bH1);
        }
      }
    }
    __syncthreads();
  }

  if(ctx_en&&blockIdx.x==1){
    const int b=row0/HWSZ,p0=row0%HWSZ;
#pragma unroll
    for(int mi=0;mi<2;mi++){
      int rl=wm+mi*16+gid;
#pragma unroll
      for(int ni=0;ni<8;ni++){
        int c=wn+ni*8+2*tig;
        float b0=__ldg(bi+c),b1=__ldg(bi+c+1);
        g_ctx[(size_t)(b*CC+c)*HWSZ+p0+rl]=acc[mi][ni][0]+b0;
        g_ctx[(size_t)(b*CC+c+1)*HWSZ+p0+rl]=acc[mi][ni][1]+b1;
        g_ctx[(size_t)(b*CC+c)*HWSZ+p0+rl+8]=acc[mi][ni][2]+b0;
        g_ctx[(size_t)(b*CC+c+1)*HWSZ+p0+rl+8]=acc[mi][ni][3]+b1;
      }
    }
  }else{
    float* dst=dq?dq:g_q;
#pragma unroll
    for(int mi=0;mi<2;mi++){
      int r0=row0+wm+mi*16+gid;
#pragma unroll
      for(int ni=0;ni<8;ni++){
        int c=wn+ni*8+2*tig;
        float b0=__ldg(bi+c),b1=__ldg(bi+c+1);
        *(float2*)(dst+(size_t)r0*CC+c)=make_float2(acc[mi][ni][0]+b0,acc[mi][ni][1]+b1);
        *(float2*)(dst+(size_t)(r0+8)*CC+c)=make_float2(acc[mi][ni][2]+b0,acc[mi][ni][3]+b1);
      }
    }
  }
}

// ============ gates: x @ Wf[:,256:260] + bf[256:260]
__global__ __launch_bounds__(256) void gates_kernel(
  const float* __restrict__ x,const float* __restrict__ Wf,const float* __restrict__ bf)
{
  const int warp=threadIdx.x>>5,lane=threadIdx.x&31;
  const int n=blockIdx.x*8+warp;
  float4 xv=*(const float4*)(x+(size_t)n*CC+lane*4);
  float s0=0.f,s1=0.f,s2=0.f,s3=0.f;
  float xa[4]={xv.x,xv.y,xv.z,xv.w};
#pragma unroll
  for(int t=0;t<4;t++){
    const float* wr=Wf+(size_t)(lane*4+t)*260+256;
    s0=fmaf(xa[t],__ldg(wr+0),s0); s1=fmaf(xa[t],__ldg(wr+1),s1);
    s2=fmaf(xa[t],__ldg(wr+2),s2); s3=fmaf(xa[t],__ldg(wr+3),s3);
  }
#pragma unroll
  for(int off=16;off;off>>=1){
    s0+=__shfl_xor_sync(0xffffffffu,s0,off); s1+=__shfl_xor_sync(0xffffffffu,s1,off);
    s2+=__shfl_xor_sync(0xffffffffu,s2,off); s3+=__shfl_xor_sync(0xffffffffu,s3,off);
  }
  if(lane==0){
    float4 g={s0+__ldg(bf+256),s1+__ldg(bf+257),s2+__ldg(bf+258),s3+__ldg(bf+259)};
    *(float4*)(g_gates+(size_t)n*4)=g;
  }
}

// ============ fused 3-level depthwise conv, 4-wide vectorized outputs.
__global__ __launch_bounds__(256) void conv_kernel(
  const float* __restrict__ kw0,const float* __restrict__ kw1,const float* __restrict__ kw2)
{
  __shared__ float buf0[44*44+8];
  __shared__ float buf1[42*44];
  __shared__ float buf2[38*40];
  __shared__ float wts[83];
  __shared__ float red[256];
  const int tid=threadIdx.x;
  const int ty0=(blockIdx.x/3)*32,tx0=(blockIdx.x%3)*32;
  const int c=blockIdx.y,b=blockIdx.z;
  const float* src=g_ctx+(size_t)(b*CC+c)*HWSZ;

  if(tid<9) wts[tid]=__ldg(kw0+tid*CC+c);
  else if(tid<34) wts[tid]=__ldg(kw1+(tid-9)*CC+c);
  else if(tid<83) wts[tid]=__ldg(kw2+(tid-34)*CC+c);
  if(tid>=248) buf0[44*44+(tid-248)]=0.0f;

  for(int idx=tid;idx<44*44;idx+=256){
    int ly=idx/44,lx=idx-ly*44;
    int gy=ty0-6+ly,gx=tx0-6+lx;
    float v=0.0f;
    if(gy>=0&&gy<HH&&gx>=0&&gx<WW) v=src[gy*WW+gx];
    buf0[idx]=v;
  }
  __syncthreads();

  for(int g=tid;g<42*11;g+=256){
    int oy=g/11,x0=(g-oy*11)*4;
    float o0=0.f,o1=0.f,o2=0.f,o3=0.f;
#pragma unroll
    for(int i=0;i<3;i++){
      const float* r=&buf0[(oy+i)*44+x0];
      float4 p=*(const float4*)r,q=*(const float4*)(r+4);
      float w0=wts[i*3],w1=wts[i*3+1],w2=wts[i*3+2];
      o0=fmaf(p.x,w0,o0);o0=fmaf(p.y,w1,o0);o0=fmaf(p.z,w2,o0);
      o1=fmaf(p.y,w0,o1);o1=fmaf(p.z,w1,o1);o1=fmaf(p.w,w2,o1);
      o2=fmaf(p.z,w0,o2);o2=fmaf(p.w,w1,o2);o2=fmaf(q.x,w2,o2);
      o3=fmaf(p.w,w0,o3);o3=fmaf(q.x,w1,o3);o3=fmaf(q.y,w2,o3);
    }
    int gy=ty0-5+oy,gxb=tx0-5+x0;
    bool iny=(gy>=0)&(gy<HH);
    float* dst=&buf1[oy*44+x0];
    dst[0]=(iny&(gxb>=0)&(gxb<WW))?gelu_exact(o0):0.f;
    dst[1]=(iny&(gxb+1>=0)&(gxb+1<WW))?gelu_exact(o1):0.f;
    dst[2]=(iny&(gxb+2>=0)&(gxb+2<WW))?gelu_exact(o2):0.f;
    dst[3]=(iny&(gxb+3>=0)&(gxb+3<WW))?gelu_exact(o3):0.f;
  }
  __syncthreads();

  for(int g=tid;g<38*10;g+=256){
    int oy=g/10,x0=(g-oy*10)*4;
    float o0=0.f,o1=0.f,o2=0.f,o3=0.f;
#pragma unroll
    for(int i=0;i<5;i++){
      const float* r=&buf1[(oy+i)*44+x0];
      float4 p=*(const float4*)r,q=*(const float4*)(r+4);
      float f[8]={p.x,p.y,p.z,p.w,q.x,q.y,q.z,q.w};
#pragma unroll
      for(int j=0;j<5;j++){
        float w=wts[9+i*5+j];
        o0=fmaf(f[j],w,o0); o1=fmaf(f[j+1],w,o1);
        o2=fmaf(f[j+2],w,o2); o3=fmaf(f[j+3],w,o3);
      }
    }
    int gy=ty0-3+oy,gxb=tx0-3+x0;
    bool iny=(gy>=0)&(gy<HH);
    float* dst=&buf2[oy*40+x0];
    dst[0]=(iny&(gxb>=0)&(gxb<WW))?gelu_exact(o0):0.f;
    dst[1]=(iny&(gxb+1>=0)&(gxb+1<WW))?gelu_exact(o1):0.f;
    dst[2]=(iny&(gxb+2>=0)&(gxb+2<WW))?gelu_exact(o2):0.f;
    dst[3]=(iny&(gxb+3>=0)&(gxb+3<WW))?gelu_exact(o3):0.f;
  }
  __syncthreads();

  {
    int oy=tid>>3,x0=(tid&7)*4;
    float o0=0.f,o1=0.f,o2=0.f,o3=0.f;
#pragma unroll
    for(int i=0;i<7;i++){
      const float* r=&buf2[(oy+i)*40+x0];
      float4 p=*(const float4*)r,q=*(const float4*)(r+4),s4=*(const float4*)(r+8);
      float f[12]={p.x,p.y,p.z,p.w,q.x,q.y,q.z,q.w,s4.x,s4.y,s4.z,s4.w};
#pragma unroll
      for(int j=0;j<7;j++){
        float w=wts[34+i*7+j];
        o0=fmaf(f[j],w,o0); o1=fmaf(f[j+1],w,o1);
        o2=fmaf(f[j+2],w,o2); o3=fmaf(f[j+3],w,o3);
      }
    }
    float oo[4]={o0,o1,o2,o3},psum=0.0f;
    int gy=ty0+oy;
    float* dstall=g_ctxall+(size_t)(b*CC+c)*HWSZ+gy*WW;
#pragma unroll
    for(int d=0;d<4;d++){
      float c3=gelu_exact(oo[d]);
      psum+=c3;
      int gx=tx0+x0+d,n=b*HWSZ+gy*WW+gx;
      float4 g=*(const float4*)(g_gates+(size_t)n*4);
      dstall[gx]=buf1[(oy+5)*44+(x0+d+5)]*g.x+buf2[(oy+3)*40+(x0+d+3)]*g.y+c3*g.z;
    }
    red[tid]=psum;
  }
  __syncthreads();
#pragma unroll
  for(int s=128;s>0;s>>=1){
    if(tid<s) red[tid]+=red[tid+s];
    __syncthreads();
  }
  if(tid==0) atomicAdd(&g_pool[b*CC+c],red[0]);
}

__global__ void poolm_kernel(){
  g_cg[blockIdx.x*CC+threadIdx.x]=gelu_exact(g_pool[blockIdx.x*CC+threadIdx.x]*(1.0f/(float)HWSZ));
}

// ============ GEMM2 (3xTF32): modulator + q-mult + LayerNorm.  A staged [k][m].
__global__ __launch_bounds__(256) void gemm2_kernel(
  const float* __restrict__ Wh,const float* __restrict__ bh,
  const float* __restrict__ gamma,const float* __restrict__ beta)
{
  __shared__ float AsH[16*BST],AsL[16*BST],BsH[16*BST],BsL[16*BST];
  __shared__ float sg3[128],scg[128];
  __shared__ float redS[128][8],redQ[128][8];
  __shared__ float smu[128],srs[128];
  const int tid=threadIdx.x,lane=tid&31,w=tid>>5;
  const int wm=(w&3)*32,wn=(w>>2)*64,gid=lane>>2,tig=lane&3;
  const int row0=blockIdx.x*128,b=row0/HWSZ,p0=row0%HWSZ;

  if(tid<128){ sg3[tid]=g_gates[(size_t)(row0+tid)*4+3]; scg[tid]=g_cg[b*CC+tid]; }
  __syncthreads();

  float acc[2][8][4];
#pragma unroll
  for(int mi=0;mi<2;mi++)
#pragma unroll
    for(int ni=0;ni<8;ni++)
#pragma unroll
      for(int r=0;r<4;r++) acc[mi][ni][r]=0.0f;

  for(int kc=0;kc<128;kc+=16){
#pragma unroll
    for(int it=0;it<2;it++){
      int f=tid+256*it,k=f>>5,mq=(f&31)*4;
      float4 v=*(const float4*)(g_ctxall+(size_t)(b*CC+kc+k)*HWSZ+p0+mq);
      float cg=scg[kc+k];
      v.x+=sg3[mq]*cg; v.y+=sg3[mq+1]*cg; v.z+=sg3[mq+2]*cg; v.w+=sg3[mq+3]*cg;
      float4 h,l; split4(v,&h,&l);
      *(float4*)&AsH[k*BST+mq]=h; *(float4*)&AsL[k*BST+mq]=l;
    }
#pragma unroll
    for(int it=0;it<2;it++){
      int f=tid+256*it,k=f>>5,nq=(f&31)*4;
      float4 h,l,v=*(const float4*)(Wh+(size_t)(kc+k)*CC+nq);
      split4(v,&h,&l);
      *(float4*)&BsH[k*BST+nq]=h; *(float4*)&BsL[k*BST+nq]=l;
    }
    __syncthreads();
#pragma unroll
    for(int s=0;s<2;s++){
      int kb=s*8;
      uint32_t aH[2][4],aL[2][4];
#pragma unroll
      for(int mi=0;mi<2;mi++){
        int m0=wm+mi*16+gid;
        aH[mi][0]=__float_as_uint(AsH[(kb+tig)*BST+m0]);
        aH[mi][1]=__float_as_uint(AsH[(kb+tig)*BST+m0+8]);
        aH[mi][2]=__float_as_uint(AsH[(kb+tig+4)*BST+m0]);
        aH[mi][3]=__float_as_uint(AsH[(kb+tig+4)*BST+m0+8]);
        aL[mi][0]=__float_as_uint(AsL[(kb+tig)*BST+m0]);
        aL[mi][1]=__float_as_uint(AsL[(kb+tig)*BST+m0+8]);
        aL[mi][2]=__float_as_uint(AsL[(kb+tig+4)*BST+m0]);
        aL[mi][3]=__float_as_uint(AsL[(kb+tig+4)*BST+m0+8]);
      }
#pragma unroll
      for(int ni=0;ni<8;ni++){
        int nc=wn+ni*8+gid;
        uint32_t bH0=__float_as_uint(BsH[(kb+tig)*BST+nc]);
        uint32_t bH1=__float_as_uint(BsH[(kb+tig+4)*BST+nc]);
        uint32_t bL0=__float_as_uint(BsL[(kb+tig)*BST+nc]);
        uint32_t bL1=__float_as_uint(BsL[(kb+tig+4)*BST+nc]);
#pragma unroll
        for(int mi=0;mi<2;mi++){
          mma8(acc[mi][ni],aH[mi][0],aH[mi][1],aH[mi][2],aH[mi][3],bH0,bH1);
          mma8(acc[mi][ni],aH[mi][0],aH[mi][1],aH[mi][2],aH[mi][3],bL0,bL1);
          mma8(acc[mi][ni],aL[mi][0],aL[mi][1],aL[mi][2],aL[mi][3],bH0,bH1);
        }
      }
    }
    __syncthreads();
  }

  float ps4[4]={0.f,0.f,0.f,0.f},pq4[4]={0.f,0.f,0.f,0.f};
#pragma unroll
  for(int mi=0;mi<2;mi++){
    int r0=row0+wm+mi*16+gid;
#pragma unroll
    for(int ni=0;ni<8;ni++){
      int cc2=wn+ni*8+2*tig;
      float bh0=__ldg(bh+cc2),bh1=__ldg(bh+cc2+1);
      float2 q0=*(const float2*)(g_q+(size_t)r0*CC+cc2);
      float2 q1=*(const float2*)(g_q+(size_t)(r0+8)*CC+cc2);
      float v0=q0.x*(acc[mi][ni][0]+bh0),v1=q0.y*(acc[mi][ni][1]+bh1);
      float v2=q1.x*(acc[mi][ni][2]+bh0),v3=q1.y*(acc[mi][ni][3]+bh1);
      acc[mi][ni][0]=v0; acc[mi][ni][1]=v1; acc[mi][ni][2]=v2; acc[mi][ni][3]=v3;
      ps4[mi*2]+=v0+v1; pq4[mi*2]=fmaf(v0,v0,fmaf(v1,v1,pq4[mi*2]));
      ps4[mi*2+1]+=v2+v3; pq4[mi*2+1]=fmaf(v2,v2,fmaf(v3,v3,pq4[mi*2+1]));
    }
  }
  const int col8=(w>>2)*4+tig;
#pragma unroll
  for(int mi=0;mi<2;mi++){
    int rl=wm+mi*16+gid;
    redS[rl][col8]=ps4[mi*2];   redQ[rl][col8]=pq4[mi*2];
    redS[rl+8][col8]=ps4[mi*2+1]; redQ[rl+8][col8]=pq4[mi*2+1];
  }
  __syncthreads();
  if(tid<128){
    float s=0.f,sq=0.f;
#pragma unroll
    for(int t=0;t<8;t++){ s+=redS[tid][t]; sq+=redQ[tid][t]; }
    float mu=s*(1.0f/CC),var=sq*(1.0f/CC)-mu*mu;
    smu[tid]=mu; srs[tid]=rsqrtf(var+LN_EPS);
  }
  __syncthreads();
#pragma unroll
  for(int mi=0;mi<2;mi++){
    int rl=wm+mi*16+gid,r0=row0+rl;
    float mu0=smu[rl],rs0=srs[rl],mu1=smu[rl+8],rs1=srs[rl+8];
#pragma unroll
    for(int ni=0;ni<8;ni++){
      int cc2=wn+ni*8+2*tig;
      float gm0=__ldg(gamma+cc2),gm1=__ldg(gamma+cc2+1);
      float be0=__ldg(beta+cc2),be1=__ldg(beta+cc2+1);
      *(float2*)(g_xout+(size_t)r0*CC+cc2)=make_float2(
        fmaf((acc[mi][ni][0]-mu0)*rs0,gm0,be0),fmaf((acc[mi][ni][1]-mu0)*rs0,gm1,be1));
      *(float2*)(g_xout+(size_t)(r0+8)*CC+cc2)=make_float2(
        fmaf((acc[mi][ni][2]-mu1)*rs1,gm0,be0),fmaf((acc[mi][ni][3]-mu1)*rs1,gm1,be1));
    }
  }
}

// ---------------- launcher ---------------------------------------------------
extern "C" void kernel_launch(void* const* d_in,const int* in_sizes,int n_in,
                              void* d_out,int out_size)
{
  const float *x=0,*Wf=0,*bf=0,*Wh=0,*bh=0,*gamma=0,*beta=0,*Wp=0,*bp=0,*k0=0,*k1=0,*k2=0;
  int n16384=0,n128=0;
  for(int i=0;i<n_in;i++){
    const float* p=(const float*)d_in[i];
    switch(in_sizes[i]){
      case 18874368: x=p; break;
      case 33280:    Wf=p; break;
      case 260:      bf=p; break;
      case 16384:    if(n16384++==0) Wh=p; else Wp=p; break;
      case 128:
        if(n128==0) bh=p; else if(n128==1) gamma=p;
        else if(n128==2) beta=p; else bp=p;
        n128++; break;
      case 1152: k0=p; break;
      case 3200: k1=p; break;
      case 6272: k2=p; break;
      default: break;
    }
  }
  float* out=(float*)d_out;

  zero_pool_kernel<<<8,256>>>();
  gemmA_kernel<<<dim3(2,NPIX/128),256>>>(x,Wf,260,bf,0,1);            // GEMM1: q + ctx
  gates_kernel<<<NPIX/8,256>>>(x,Wf,bf);
  conv_kernel<<<dim3(9,CC,BB),256>>>(k0,k1,k2);
  poolm_kernel<<<BB,CC>>>();
  gemm2_kernel<<<NPIX/128,256>>>(Wh,bh,gamma,beta);
  gemmA_kernel<<<dim3(1,NPIX/128),256>>>((const float*)0,Wp,CC,bp,out,0); // GEMM3: A=g_xout
  (void)out_size;
}

// round 13
// speedup vs baseline: 2.4277x; 1.0616x over previous
#include <cuda_runtime.h>
#include <math.h>
#include <stdint.h>

#define BB 16
#define HH 96
#define WW 96
#define CC 128
#define HWSZ 9216
#define NPIX 147456
#define LN_EPS 1e-3f
#define AST 20
#define BST 136

__device__ float g_q[NPIX*CC];
__device__ float g_ctx[NPIX*CC];
__device__ float g_ctxall[NPIX*CC];
__device__ float g_gates[NPIX*4];
__device__ float g_xout[NPIX*CC];
__device__ float g_pool[BB*CC];
__device__ float g_cg[BB*CC];

__device__ __forceinline__ float gelu_exact(float v){return 0.5f*v*(1.0f+erff(v*0.70710678118654752f));}
__device__ __forceinline__ float to_tf32(float x){float r;asm("cvt.rna.tf32.f32 %0, %1;":"=f"(r):"f"(x));return r;}
__device__ __forceinline__ void split4(float4 v,float4* h,float4* l){
  float h0=to_tf32(v.x),h1=to_tf32(v.y),h2=to_tf32(v.z),h3=to_tf32(v.w);
  *h=make_float4(h0,h1,h2,h3);
  *l=make_float4(to_tf32(v.x-h0),to_tf32(v.y-h1),to_tf32(v.z-h2),to_tf32(v.w-h3));
}
__device__ __forceinline__ void mma8(float* c,uint32_t a0,uint32_t a1,uint32_t a2,uint32_t a3,uint32_t b0,uint32_t b1){
  asm volatile("mma.sync.aligned.m16n8k8.row.col.f32.tf32.tf32.f32 {%0,%1,%2,%3},{%4,%5,%6,%7},{%8,%9},{%0,%1,%2,%3};"
    :"+f"(c[0]),"+f"(c[1]),"+f"(c[2]),"+f"(c[3]):"r"(a0),"r"(a1),"r"(a2),"r"(a3),"r"(b0),"r"(b1));
}

__global__ void zero_pool_kernel(){
  int i=blockIdx.x*blockDim.x+threadIdx.x;
  if(i<BB*CC) g_pool[i]=0.0f;
}

// ============ tensor-core GEMM (3xTF32) with register prefetch.
// A==nullptr -> g_xout. ctx_en: bx==1 -> NCHW g_ctx; bx==0 also computes gates.
__global__ __launch_bounds__(256) void gemmA_kernel(
  const float* __restrict__ A,const float* __restrict__ W,int ldw,
  const float* __restrict__ bias,float* __restrict__ dq,int ctx_en)
{
  __shared__ float AsH[128*AST],AsL[128*AST],BsH[16*BST],BsL[16*BST];
  __shared__ float wg[512];
  const int tid=threadIdx.x,lane=tid&31,w=tid>>5;
  const int wm=(w&3)*32,wn=(w>>2)*64,gid=lane>>2,tig=lane&3;
  const int row0=blockIdx.y*128,n0=blockIdx.x*128;
  const float* Ap=A?A:(const float*)g_xout;
  const float* bi=bias+n0;
  const int do_gates=ctx_en&&(blockIdx.x==0);
  if(do_gates){
    for(int idx=tid;idx<512;idx+=256){int k=idx>>2,j=idx&3; wg[idx]=__ldg(W+(size_t)k*ldw+256+j);}
  }
  float ga0=0.f,ga1=0.f;
  const int gm=tid>>1,gjp=(tid&1)*2;

  float acc[2][8][4];
#pragma unroll
  for(int mi=0;mi<2;mi++)
#pragma unroll
    for(int ni=0;ni<8;ni++)
#pragma unroll
      for(int r=0;r<4;r++) acc[mi][ni][r]=0.0f;

  // per-thread staging coords
  const int am0=tid>>2, akq=(tid&3)*4;          // A: it adds +64 rows
  const int bk0=tid>>5, bnq=(tid&31)*4;         // B: it adds +8 k

  float4 pA[2],pB[2];
#pragma unroll
  for(int it=0;it<2;it++){
    pA[it]=*(const float4*)(Ap+(size_t)(row0+am0+64*it)*CC+akq);
    pB[it]=*(const float4*)(W+(size_t)(bk0+8*it)*ldw+n0+bnq);
  }

  for(int kc=0;kc<128;kc+=16){
#pragma unroll
    for(int it=0;it<2;it++){
      float4 h,l;
      split4(pA[it],&h,&l);
      *(float4*)&AsH[(am0+64*it)*AST+akq]=h; *(float4*)&AsL[(am0+64*it)*AST+akq]=l;
      split4(pB[it],&h,&l);
      *(float4*)&BsH[(bk0+8*it)*BST+bnq]=h; *(float4*)&BsL[(bk0+8*it)*BST+bnq]=l;
    }
    __syncthreads();
    if(kc<112){
#pragma unroll
      for(int it=0;it<2;it++){
        pA[it]=*(const float4*)(Ap+(size_t)(row0+am0+64*it)*CC+kc+16+akq);
        pB[it]=*(const float4*)(W+(size_t)(kc+16+bk0+8*it)*ldw+n0+bnq);
      }
    }
#pragma unroll
    for(int s=0;s<2;s++){
      int kb=s*8;
      uint32_t aH[2][4],aL[2][4];
#pragma unroll
      for(int mi=0;mi<2;mi++){
        int m0=wm+mi*16+gid;
        aH[mi][0]=__float_as_uint(AsH[m0*AST+kb+tig]);
        aH[mi][1]=__float_as_uint(AsH[(m0+8)*AST+kb+tig]);
        aH[mi][2]=__float_as_uint(AsH[m0*AST+kb+tig+4]);
        aH[mi][3]=__float_as_uint(AsH[(m0+8)*AST+kb+tig+4]);
        aL[mi][0]=__float_as_uint(AsL[m0*AST+kb+tig]);
        aL[mi][1]=__float_as_uint(AsL[(m0+8)*AST+kb+tig]);
        aL[mi][2]=__float_as_uint(AsL[m0*AST+kb+tig+4]);
        aL[mi][3]=__float_as_uint(AsL[(m0+8)*AST+kb+tig+4]);
      }
#pragma unroll
      for(int ni=0;ni<8;ni++){
        int nc=wn+ni*8+gid;
        uint32_t bH0=__float_as_uint(BsH[(kb+tig)*BST+nc]);
        uint32_t bH1=__float_as_uint(BsH[(kb+tig+4)*BST+nc]);
        uint32_t bL0=__float_as_uint(BsL[(kb+tig)*BST+nc]);
        uint32_t bL1=__float_as_uint(BsL[(kb+tig+4)*BST+nc]);
#pragma unroll
        for(int mi=0;mi<2;mi++){
          mma8(acc[mi][ni],aH[mi][0],aH[mi][1],aH[mi][2],aH[mi][3],bH0,bH1);
          mma8(acc[mi][ni],aH[mi][0],aH[mi][1],aH[mi][2],aH[mi][3],bL0,bL1);
          mma8(acc[mi][ni],aL[mi][0],aL[mi][1],aL[mi][2],aL[mi][3],bH0,bH1);
        }
      }
    }
    if(do_gates){
#pragma unroll
      for(int k2=0;k2<16;k2++){
        float a=AsH[gm*AST+k2]+AsL[gm*AST+k2];
        ga0=fmaf(a,wg[(kc+k2)*4+gjp],ga0);
        ga1=fmaf(a,wg[(kc+k2)*4+gjp+1],ga1);
      }
    }
    __syncthreads();
  }

  if(do_gates){
    *(float2*)(g_gates+(size_t)(row0+gm)*4+gjp)=
      make_float2(ga0+__ldg(bias+256+gjp),ga1+__ldg(bias+257+gjp));
  }

  if(ctx_en&&blockIdx.x==1){
    const int b=row0/HWSZ,p0=row0%HWSZ;
#pragma unroll
    for(int mi=0;mi<2;mi++){
      int rl=wm+mi*16+gid;
#pragma unroll
      for(int ni=0;ni<8;ni++){
        int c=wn+ni*8+2*tig;
        float b0=__ldg(bi+c),b1=__ldg(bi+c+1);
        g_ctx[(size_t)(b*CC+c)*HWSZ+p0+rl]=acc[mi][ni][0]+b0;
        g_ctx[(size_t)(b*CC+c+1)*HWSZ+p0+rl]=acc[mi][ni][1]+b1;
        g_ctx[(size_t)(b*CC+c)*HWSZ+p0+rl+8]=acc[mi][ni][2]+b0;
        g_ctx[(size_t)(b*CC+c+1)*HWSZ+p0+rl+8]=acc[mi][ni][3]+b1;
      }
    }
  }else{
    float* dst=dq?dq:g_q;
#pragma unroll
    for(int mi=0;mi<2;mi++){
      int r0=row0+wm+mi*16+gid;
#pragma unroll
      for(int ni=0;ni<8;ni++){
        int c=wn+ni*8+2*tig;
        float b0=__ldg(bi+c),b1=__ldg(bi+c+1);
        *(float2*)(dst+(size_t)r0*CC+c)=make_float2(acc[mi][ni][0]+b0,acc[mi][ni][1]+b1);
        *(float2*)(dst+(size_t)(r0+8)*CC+c)=make_float2(acc[mi][ni][2]+b0,acc[mi][ni][3]+b1);
      }
    }
  }
}

// ============ fused 3-level depthwise conv, 48x48 tiles, 4-wide vectorized.
__global__ __launch_bounds__(256) void conv_kernel(
  const float* __restrict__ kw0,const float* __restrict__ kw1,const float* __restrict__ kw2)
{
  __shared__ float buf0[60*60+8];
  __shared__ float buf1[58*60];
  __shared__ float buf2[54*56];
  __shared__ float wts[83];
  __shared__ float red8[8];
  const int tid=threadIdx.x,lane=tid&31,warp=tid>>5;
  const int ty0=(blockIdx.x>>1)*48,tx0=(blockIdx.x&1)*48;
  const int c=blockIdx.y,b=blockIdx.z;
  const float* src=g_ctx+(size_t)(b*CC+c)*HWSZ;

  if(tid<9) wts[tid]=__ldg(kw0+tid*CC+c);
  else if(tid<34) wts[tid]=__ldg(kw1+(tid-9)*CC+c);
  else if(tid<83) wts[tid]=__ldg(kw2+(tid-34)*CC+c);

  for(int idx=tid;idx<3600;idx+=256){
    int ly=idx/60,lx=idx-ly*60;
    int gy=ty0-6+ly,gx=tx0-6+lx;
    float v=0.0f;
    if(gy>=0&&gy<HH&&gx>=0&&gx<WW) v=src[gy*WW+gx];
    buf0[idx]=v;
  }
  __syncthreads();

  // level 0: 3x3 -> 58 rows x 60 cols (58/59 scratch)
  for(int g=tid;g<58*15;g+=256){
    int oy=g/15,x0=(g-oy*15)*4;
    float o0=0.f,o1=0.f,o2=0.f,o3=0.f;
#pragma unroll
    for(int i=0;i<3;i++){
      const float* r=&buf0[(oy+i)*60+x0];
      float4 p=*(const float4*)r,q=*(const float4*)(r+4);
      float w0=wts[i*3],w1=wts[i*3+1],w2=wts[i*3+2];
      o0=fmaf(p.x,w0,o0);o0=fmaf(p.y,w1,o0);o0=fmaf(p.z,w2,o0);
      o1=fmaf(p.y,w0,o1);o1=fmaf(p.z,w1,o1);o1=fmaf(p.w,w2,o1);
      o2=fmaf(p.z,w0,o2);o2=fmaf(p.w,w1,o2);o2=fmaf(q.x,w2,o2);
      o3=fmaf(p.w,w0,o3);o3=fmaf(q.x,w1,o3);o3=fmaf(q.y,w2,o3);
    }
    int gy=ty0-5+oy,gxb=tx0-5+x0;
    bool iny=(gy>=0)&(gy<HH);
    float* dst=&buf1[oy*60+x0];
    dst[0]=(iny&(gxb>=0)&(gxb<WW))?gelu_exact(o0):0.f;
    dst[1]=(iny&(gxb+1>=0)&(gxb+1<WW))?gelu_exact(o1):0.f;
    dst[2]=(iny&(gxb+2>=0)&(gxb+2<WW))?gelu_exact(o2):0.f;
    dst[3]=(iny&(gxb+3>=0)&(gxb+3<WW))?gelu_exact(o3):0.f;
  }
  __syncthreads();

  // level 1: 5x5 -> 54 rows x 56 cols (54/55 scratch)
  for(int g=tid;g<54*14;g+=256){
    int oy=g/14,x0=(g-oy*14)*4;
    float o0=0.f,o1=0.f,o2=0.f,o3=0.f;
#pragma unroll
    for(int i=0;i<5;i++){
      const float* r=&buf1[(oy+i)*60+x0];
      float4 p=*(const float4*)r,q=*(const float4*)(r+4);
      float f[8]={p.x,p.y,p.z,p.w,q.x,q.y,q.z,q.w};
#pragma unroll
      for(int j=0;j<5;j++){
        float w=wts[9+i*5+j];
        o0=fmaf(f[j],w,o0); o1=fmaf(f[j+1],w,o1);
        o2=fmaf(f[j+2],w,o2); o3=fmaf(f[j+3],w,o3);
      }
    }
    int gy=ty0-3+oy,gxb=tx0-3+x0;
    bool iny=(gy>=0)&(gy<HH);
    float* dst=&buf2[oy*56+x0];
    dst[0]=(iny&(gxb>=0)&(gxb<WW))?gelu_exact(o0):0.f;
    dst[1]=(iny&(gxb+1>=0)&(gxb+1<WW))?gelu_exact(o1):0.f;
    dst[2]=(iny&(gxb+2>=0)&(gxb+2<WW))?gelu_exact(o2):0.f;
    dst[3]=(iny&(gxb+3>=0)&(gxb+3<WW))?gelu_exact(o3):0.f;
  }
  __syncthreads();

  // level 2: 7x7 -> 48x48 + gated accumulate + pool partial
  float psum=0.0f;
  for(int g=tid;g<48*12;g+=256){
    int oy=g/12,x0=(g-oy*12)*4;
    float o0=0.f,o1=0.f,o2=0.f,o3=0.f;
#pragma unroll
    for(int i=0;i<7;i++){
      const float* r=&buf2[(oy+i)*56+x0];
      float4 p=*(const float4*)r,q=*(const float4*)(r+4),s4=*(const float4*)(r+8);
      float f[12]={p.x,p.y,p.z,p.w,q.x,q.y,q.z,q.w,s4.x,s4.y,s4.z,s4.w};
#pragma unroll
      for(int j=0;j<7;j++){
        float w=wts[34+i*7+j];
        o0=fmaf(f[j],w,o0); o1=fmaf(f[j+1],w,o1);
        o2=fmaf(f[j+2],w,o2); o3=fmaf(f[j+3],w,o3);
      }
    }
    float oo[4]={o0,o1,o2,o3};
    int gy=ty0+oy;
    float* dstall=g_ctxall+(size_t)(b*CC+c)*HWSZ+gy*WW;
#pragma unroll
    for(int d=0;d<4;d++){
      float c3=gelu_exact(oo[d]);
      psum+=c3;
      int gx=tx0+x0+d,n=b*HWSZ+gy*WW+gx;
      float4 gg=*(const float4*)(g_gates+(size_t)n*4);
      dstall[gx]=buf1[(oy+5)*60+(x0+d+5)]*gg.x+buf2[(oy+3)*56+(x0+d+3)]*gg.y+c3*gg.z;
    }
  }
#pragma unroll
  for(int off=16;off;off>>=1) psum+=__shfl_xor_sync(0xffffffffu,psum,off);
  if(lane==0) red8[warp]=psum;
  __syncthreads();
  if(tid<8){
    float s=red8[tid];
    s+=__shfl_xor_sync(0xffu,s,4);
    s+=__shfl_xor_sync(0xffu,s,2);
    s+=__shfl_xor_sync(0xffu,s,1);
    if(tid==0) atomicAdd(&g_pool[b*CC+c],s);
  }
}

__global__ void poolm_kernel(){
  g_cg[blockIdx.x*CC+threadIdx.x]=gelu_exact(g_pool[blockIdx.x*CC+threadIdx.x]*(1.0f/(float)HWSZ));
}

// ============ GEMM2 (3xTF32) with register prefetch: modulator + q-mult + LN.
__global__ __launch_bounds__(256) void gemm2_kernel(
  const float* __restrict__ Wh,const float* __restrict__ bh,
  const float* __restrict__ gamma,const float* __restrict__ beta)
{
  __shared__ float AsH[16*BST],AsL[16*BST],BsH[16*BST],BsL[16*BST];
  __shared__ float sg3[128],scg[128];
  __shared__ float redS[128][8],redQ[128][8];
  __shared__ float smu[128],srs[128];
  const int tid=threadIdx.x,lane=tid&31,w=tid>>5;
  const int wm=(w&3)*32,wn=(w>>2)*64,gid=lane>>2,tig=lane&3;
  const int row0=blockIdx.x*128,b=row0/HWSZ,p0=row0%HWSZ;

  if(tid<128){ sg3[tid]=g_gates[(size_t)(row0+tid)*4+3]; scg[tid]=g_cg[b*CC+tid]; }
  __syncthreads();

  float acc[2][8][4];
#pragma unroll
  for(int mi=0;mi<2;mi++)
#pragma unroll
    for(int ni=0;ni<8;ni++)
#pragma unroll
      for(int r=0;r<4;r++) acc[mi][ni][r]=0.0f;

  const int sk0=tid>>5, sq0=(tid&31)*4;   // it adds +8 k

  float4 pA[2],pB[2];
#pragma unroll
  for(int it=0;it<2;it++){
    pA[it]=*(const float4*)(g_ctxall+(size_t)(b*CC+sk0+8*it)*HWSZ+p0+sq0);
    pB[it]=*(const float4*)(Wh+(size_t)(sk0+8*it)*CC+sq0);
  }

  for(int kc=0;kc<128;kc+=16){
#pragma unroll
    for(int it=0;it<2;it++){
      int k=sk0+8*it;
      float4 v=pA[it];
      float cg=scg[kc+k];
      v.x+=sg3[sq0]*cg; v.y+=sg3[sq0+1]*cg; v.z+=sg3[sq0+2]*cg; v.w+=sg3[sq0+3]*cg;
      float4 h,l; split4(v,&h,&l);
      *(float4*)&AsH[k*BST+sq0]=h; *(float4*)&AsL[k*BST+sq0]=l;
      split4(pB[it],&h,&l);
      *(float4*)&BsH[k*BST+sq0]=h; *(float4*)&BsL[k*BST+sq0]=l;
    }
    __syncthreads();
    if(kc<112){
#pragma unroll
      for(int it=0;it<2;it++){
        pA[it]=*(const float4*)(g_ctxall+(size_t)(b*CC+kc+16+sk0+8*it)*HWSZ+p0+sq0);
        pB[it]=*(const float4*)(Wh+(size_t)(kc+16+sk0+8*it)*CC+sq0);
      }
    }
#pragma unroll
    for(int s=0;s<2;s++){
      int kb=s*8;
      uint32_t aH[2][4],aL[2][4];
#pragma unroll
      for(int mi=0;mi<2;mi++){
        int m0=wm+mi*16+gid;
        aH[mi][0]=__float_as_uint(AsH[(kb+tig)*BST+m0]);
        aH[mi][1]=__float_as_uint(AsH[(kb+tig)*BST+m0+8]);
        aH[mi][2]=__float_as_uint(AsH[(kb+tig+4)*BST+m0]);
        aH[mi][3]=__float_as_uint(AsH[(kb+tig+4)*BST+m0+8]);
        aL[mi][0]=__float_as_uint(AsL[(kb+tig)*BST+m0]);
        aL[mi][1]=__float_as_uint(AsL[(kb+tig)*BST+m0+8]);
        aL[mi][2]=__float_as_uint(AsL[(kb+tig+4)*BST+m0]);
        aL[mi][3]=__float_as_uint(AsL[(kb+tig+4)*BST+m0+8]);
      }
#pragma unroll
      for(int ni=0;ni<8;ni++){
        int nc=wn+ni*8+gid;
        uint32_t bH0=__float_as_uint(BsH[(kb+tig)*BST+nc]);
        uint32_t bH1=__float_as_uint(BsH[(kb+tig+4)*BST+nc]);
        uint32_t bL0=__float_as_uint(BsL[(kb+tig)*BST+nc]);
        uint32_t bL1=__float_as_uint(BsL[(kb+tig+4)*BST+nc]);
#pragma unroll
        for(int mi=0;mi<2;mi++){
          mma8(acc[mi][ni],aH[mi][0],aH[mi][1],aH[mi][2],aH[mi][3],bH0,bH1);
          mma8(acc[mi][ni],aH[mi][0],aH[mi][1],aH[mi][2],aH[mi][3],bL0,bL1);
          mma8(acc[mi][ni],aL[mi][0],aL[mi][1],aL[mi][2],aL[mi][3],bH0,bH1);
        }
      }
    }
    __syncthreads();
  }

  float ps4[4]={0.f,0.f,0.f,0.f},pq4[4]={0.f,0.f,0.f,0.f};
#pragma unroll
  for(int mi=0;mi<2;mi++){
    int r0=row0+wm+mi*16+gid;
#pragma unroll
    for(int ni=0;ni<8;ni++){
      int cc2=wn+ni*8+2*tig;
      float bh0=__ldg(bh+cc2),bh1=__ldg(bh+cc2+1);
      float2 q0=*(const float2*)(g_q+(size_t)r0*CC+cc2);
      float2 q1=*(const float2*)(g_q+(size_t)(r0+8)*CC+cc2);
      float v0=q0.x*(acc[mi][ni][0]+bh0),v1=q0.y*(acc[mi][ni][1]+bh1);
      float v2=q1.x*(acc[mi][ni][2]+bh0),v3=q1.y*(acc[mi][ni][3]+bh1);
      acc[mi][ni][0]=v0; acc[mi][ni][1]=v1; acc[mi][ni][2]=v2; acc[mi][ni][3]=v3;
      ps4[mi*2]+=v0+v1; pq4[mi*2]=fmaf(v0,v0,fmaf(v1,v1,pq4[mi*2]));
      ps4[mi*2+1]+=v2+v3; pq4[mi*2+1]=fmaf(v2,v2,fmaf(v3,v3,pq4[mi*2+1]));
    }
  }
  const int col8=(w>>2)*4+tig;
#pragma unroll
  for(int mi=0;mi<2;mi++){
    int rl=wm+mi*16+gid;
    redS[rl][col8]=ps4[mi*2];   redQ[rl][col8]=pq4[mi*2];
    redS[rl+8][col8]=ps4[mi*2+1]; redQ[rl+8][col8]=pq4[mi*2+1];
  }
  __syncthreads();
  if(tid<128){
    float s=0.f,sq=0.f;
#pragma unroll
    for(int t=0;t<8;t++){ s+=redS[tid][t]; sq+=redQ[tid][t]; }
    float mu=s*(1.0f/CC),var=sq*(1.0f/CC)-mu*mu;
    smu[tid]=mu; srs[tid]=rsqrtf(var+LN_EPS);
  }
  __syncthreads();
#pragma unroll
  for(int mi=0;mi<2;mi++){
    int rl=wm+mi*16+gid,r0=row0+rl;
    float mu0=smu[rl],rs0=srs[rl],mu1=smu[rl+8],rs1=srs[rl+8];
#pragma unroll
    for(int ni=0;ni<8;ni++){
      int cc2=wn+ni*8+2*tig;
      float gm0=__ldg(gamma+cc2),gm1=__ldg(gamma+cc2+1);
      float be0=__ldg(beta+cc2),be1=__ldg(beta+cc2+1);
      *(float2*)(g_xout+(size_t)r0*CC+cc2)=make_float2(
        fmaf((acc[mi][ni][0]-mu0)*rs0,gm0,be0),fmaf((acc[mi][ni][1]-mu0)*rs0,gm1,be1));
      *(float2*)(g_xout+(size_t)(r0+8)*CC+cc2)=make_float2(
        fmaf((acc[mi][ni][2]-mu1)*rs1,gm0,be0),fmaf((acc[mi][ni][3]-mu1)*rs1,gm1,be1));
    }
  }
}

// ---------------- launcher ---------------------------------------------------
extern "C" void kernel_launch(void* const* d_in,const int* in_sizes,int n_in,
                              void* d_out,int out_size)
{
  const float *x=0,*Wf=0,*bf=0,*Wh=0,*bh=0,*gamma=0,*beta=0,*Wp=0,*bp=0,*k0=0,*k1=0,*k2=0;
  int n16384=0,n128=0;
  for(int i=0;i<n_in;i++){
    const float* p=(const float*)d_in[i];
    switch(in_sizes[i]){
      case 18874368: x=p; break;
      case 33280:    Wf=p; break;
      case 260:      bf=p; break;
      case 16384:    if(n16384++==0) Wh=p; else Wp=p; break;
      case 128:
        if(n128==0) bh=p; else if(n128==1) gamma=p;
        else if(n128==2) beta=p; else bp=p;
        n128++; break;
      case 1152: k0=p; break;
      case 3200: k1=p; break;
      case 6272: k2=p; break;
      default: break;
    }
  }
  float* out=(float*)d_out;

  zero_pool_kernel<<<8,256>>>();
  gemmA_kernel<<<dim3(2,NPIX/128),256>>>(x,Wf,260,bf,0,1);               // GEMM1: q + ctx + gates
  conv_kernel<<<dim3(4,CC,BB),256>>>(k0,k1,k2);
  poolm_kernel<<<BB,CC>>>();
  gemm2_kernel<<<NPIX/128,256>>>(Wh,bh,gamma,beta);
  gemmA_kernel<<<dim3(1,NPIX/128),256>>>((const float*)0,Wp,CC,bp,out,0); // GEMM3
  (void)out_size;
}

// round 17
// speedup vs baseline: 3.1680x; 1.3050x over previous
#include <cuda_runtime.h>
#include <cuda_bf16.h>
#include <math.h>
#include <stdint.h>

#define BB 16
#define HH 96
#define WW 96
#define CC 128
#define HWSZ 9216
#define NPIX 147456
#define LN_EPS 1e-3f
#define AP 12     // A smem stride in uint32 pairs (8 pairs + 4 pad)
#define BP 136    // B / gemm2-A smem stride (128 + 8)

__device__ float g_q[NPIX*CC];
__device__ float g_ctx[NPIX*CC];
__device__ float g_ctxall[NPIX*CC];
__device__ float g_gates[NPIX*4];
__device__ float g_xout[NPIX*CC];
__device__ float g_pool[BB*CC];
__device__ float g_cg[BB*CC];

__device__ __forceinline__ float gelu_exact(float v){return 0.5f*v*(1.0f+erff(v*0.70710678118654752f));}

// pack two floats' bf16 hi parts (a->low, b->high) and lo parts
__device__ __forceinline__ void bpack(float a,float b,uint32_t* hi,uint32_t* lo){
  __nv_bfloat16 h0=__float2bfloat16_rn(a),h1=__float2bfloat16_rn(b);
  float r0=a-__bfloat162float(h0),r1=b-__bfloat162float(h1);
  __nv_bfloat16 l0=__float2bfloat16_rn(r0),l1=__float2bfloat16_rn(r1);
  *hi=((uint32_t)__bfloat16_as_ushort(h1)<<16)|__bfloat16_as_ushort(h0);
  *lo=((uint32_t)__bfloat16_as_ushort(l1)<<16)|__bfloat16_as_ushort(l0);
}
__device__ __forceinline__ float2 bunpack(uint32_t u){
  return __bfloat1622float2(*(__nv_bfloat162*)&u);
}
__device__ __forceinline__ void mma16(float* c,uint32_t a0,uint32_t a1,uint32_t a2,uint32_t a3,uint32_t b0,uint32_t b1){
  asm volatile("mma.sync.aligned.m16n8k16.row.col.f32.bf16.bf16.f32 {%0,%1,%2,%3},{%4,%5,%6,%7},{%8,%9},{%0,%1,%2,%3};"
    :"+f"(c[0]),"+f"(c[1]),"+f"(c[2]),"+f"(c[3]):"r"(a0),"r"(a1),"r"(a2),"r"(a3),"r"(b0),"r"(b1));
}

__global__ void zero_pool_kernel(){
  int i=blockIdx.x*blockDim.x+threadIdx.x;
  if(i<BB*CC) g_pool[i]=0.0f;
}

// ============ bf16x2-split tensor GEMM: C = A[row0:+128] @ W[:,n0:+128] + bias
// A==nullptr -> g_xout. ctx_en: bx==1 -> NCHW g_ctx; bx==0 also computes gates.
__global__ __launch_bounds__(256) void gemmA_kernel(
  const float* __restrict__ A,const float* __restrict__ W,int ldw,
  const float* __restrict__ bias,float* __restrict__ dq,int ctx_en)
{
  __shared__ uint32_t AsH[128*AP],AsL[128*AP],BsH[8*BP],BsL[8*BP];
  __shared__ float wg[512];
  const int tid=threadIdx.x,lane=tid&31,w=tid>>5;
  const int wm=(w&3)*32,wn=(w>>2)*64,gid=lane>>2,tig=lane&3;
  const int row0=blockIdx.y*128,n0=blockIdx.x*128;
  const float* Ap=A?A:(const float*)g_xout;
  const float* bi=bias+n0;
  const int do_gates=ctx_en&&(blockIdx.x==0);
  if(do_gates){
    for(int idx=tid;idx<512;idx+=256){int k=idx>>2,j=idx&3; wg[idx]=__ldg(W+(size_t)k*ldw+256+j);}
  }
  float ga0=0.f,ga1=0.f;
  const int gm=tid>>1,gjp=(tid&1)*2;

  float acc[2][8][4];
#pragma unroll
  for(int mi=0;mi<2;mi++)
#pragma unroll
    for(int ni=0;ni<8;ni++)
#pragma unroll
      for(int r=0;r<4;r++) acc[mi][ni][r]=0.0f;

  const int am0=tid>>2, akp=(tid&3)*2;        // A: row, pair base; it adds +64 rows
  const int bkp=tid>>5, bnq=(tid&31)*4;       // B: k-pair, n quad

  float4 pA[2],pB0,pB1;
#pragma unroll
  for(int it=0;it<2;it++)
    pA[it]=*(const float4*)(Ap+(size_t)(row0+am0+64*it)*CC+akp*2);
  pB0=*(const float4*)(W+(size_t)(2*bkp)*ldw+n0+bnq);
  pB1=*(const float4*)(W+(size_t)(2*bkp+1)*ldw+n0+bnq);

  for(int kc=0;kc<128;kc+=16){
#pragma unroll
    for(int it=0;it<2;it++){
      uint32_t h0,l0,h1,l1;
      bpack(pA[it].x,pA[it].y,&h0,&l0);
      bpack(pA[it].z,pA[it].w,&h1,&l1);
      int base=(am0+64*it)*AP+akp;
      AsH[base]=h0; AsH[base+1]=h1; AsL[base]=l0; AsL[base+1]=l1;
    }
    {
      uint32_t h[4],l[4];
      bpack(pB0.x,pB1.x,&h[0],&l[0]); bpack(pB0.y,pB1.y,&h[1],&l[1]);
      bpack(pB0.z,pB1.z,&h[2],&l[2]); bpack(pB0.w,pB1.w,&h[3],&l[3]);
      *(uint4*)&BsH[bkp*BP+bnq]=make_uint4(h[0],h[1],h[2],h[3]);
      *(uint4*)&BsL[bkp*BP+bnq]=make_uint4(l[0],l[1],l[2],l[3]);
    }
    __syncthreads();
    if(kc<112){
#pragma unroll
      for(int it=0;it<2;it++)
        pA[it]=*(const float4*)(Ap+(size_t)(row0+am0+64*it)*CC+kc+16+akp*2);
      pB0=*(const float4*)(W+(size_t)(kc+16+2*bkp)*ldw+n0+bnq);
      pB1=*(const float4*)(W+(size_t)(kc+16+2*bkp+1)*ldw+n0+bnq);
    }
    uint32_t aH[2][4],aL[2][4];
#pragma unroll
    for(int mi=0;mi<2;mi++){
      int m0=wm+mi*16+gid;
      aH[mi][0]=AsH[m0*AP+tig];     aH[mi][1]=AsH[(m0+8)*AP+tig];
      aH[mi][2]=AsH[m0*AP+tig+4];   aH[mi][3]=AsH[(m0+8)*AP+tig+4];
      aL[mi][0]=AsL[m0*AP+tig];     aL[mi][1]=AsL[(m0+8)*AP+tig];
      aL[mi][2]=AsL[m0*AP+tig+4];   aL[mi][3]=AsL[(m0+8)*AP+tig+4];
    }
#pragma unroll
    for(int ni=0;ni<8;ni++){
      int nc=wn+ni*8+gid;
      uint32_t bH0=BsH[tig*BP+nc],bH1=BsH[(tig+4)*BP+nc];
      uint32_t bL0=BsL[tig*BP+nc],bL1=BsL[(tig+4)*BP+nc];
#pragma unroll
      for(int mi=0;mi<2;mi++){
        mma16(acc[mi][ni],aH[mi][0],aH[mi][1],aH[mi][2],aH[mi][3],bH0,bH1);
        mma16(acc[mi][ni],aH[mi][0],aH[mi][1],aH[mi][2],aH[mi][3],bL0,bL1);
        mma16(acc[mi][ni],aL[mi][0],aL[mi][1],aL[mi][2],aL[mi][3],bH0,bH1);
      }
    }
    if(do_gates){
#pragma unroll
      for(int kp=0;kp<8;kp++){
        float2 h=bunpack(AsH[gm*AP+kp]),l=bunpack(AsL[gm*AP+kp]);
        float ae=h.x+l.x, ao=h.y+l.y;
        int k0g=(kc+2*kp)*4;
        ga0=fmaf(ae,wg[k0g+gjp],ga0);   ga1=fmaf(ae,wg[k0g+gjp+1],ga1);
        ga0=fmaf(ao,wg[k0g+4+gjp],ga0); ga1=fmaf(ao,wg[k0g+4+gjp+1],ga1);
      }
    }
    __syncthreads();
  }

  if(do_gates){
    *(float2*)(g_gates+(size_t)(row0+gm)*4+gjp)=
      make_float2(ga0+__ldg(bias+256+gjp),ga1+__ldg(bias+257+gjp));
  }

  if(ctx_en&&blockIdx.x==1){
    const int b=row0/HWSZ,p0=row0%HWSZ;
#pragma unroll
    for(int mi=0;mi<2;mi++){
      int rl=wm+mi*16+gid;
#pragma unroll
      for(int ni=0;ni<8;ni++){
        int c=wn+ni*8+2*tig;
        float b0=__ldg(bi+c),b1=__ldg(bi+c+1);
        g_ctx[(size_t)(b*CC+c)*HWSZ+p0+rl]=acc[mi][ni][0]+b0;
        g_ctx[(size_t)(b*CC+c+1)*HWSZ+p0+rl]=acc[mi][ni][1]+b1;
        g_ctx[(size_t)(b*CC+c)*HWSZ+p0+rl+8]=acc[mi][ni][2]+b0;
        g_ctx[(size_t)(b*CC+c+1)*HWSZ+p0+rl+8]=acc[mi][ni][3]+b1;
      }
    }
  }else{
    float* dst=dq?dq:g_q;
#pragma unroll
    for(int mi=0;mi<2;mi++){
      int r0=row0+wm+mi*16+gid;
#pragma unroll
      for(int ni=0;ni<8;ni++){
        int c=wn+ni*8+2*tig;
        float b0=__ldg(bi+c),b1=__ldg(bi+c+1);
        *(float2*)(dst+(size_t)r0*CC+c)=make_float2(acc[mi][ni][0]+b0,acc[mi][ni][1]+b1);
        *(float2*)(dst+(size_t)(r0+8)*CC+c)=make_float2(acc[mi][ni][2]+b0,acc[mi][ni][3]+b1);
      }
    }
  }
}

// ============ fused 3-level depthwise conv, 48x48 tiles, 4-wide vectorized.
__global__ __launch_bounds__(256) void conv_kernel(
  const float* __restrict__ kw0,const float* __restrict__ kw1,const float* __restrict__ kw2)
{
  __shared__ float buf0[60*60+8];
  __shared__ float buf1[58*60];
  __shared__ float buf2[54*56];
  __shared__ float wts[83];
  __shared__ float red8[8];
  const int tid=threadIdx.x,lane=tid&31,warp=tid>>5;
  const int ty0=(blockIdx.x>>1)*48,tx0=(blockIdx.x&1)*48;
  const int c=blockIdx.y,b=blockIdx.z;
  const float* src=g_ctx+(size_t)(b*CC+c)*HWSZ;

  if(tid<9) wts[tid]=__ldg(kw0+tid*CC+c);
  else if(tid<34) wts[tid]=__ldg(kw1+(tid-9)*CC+c);
  else if(tid<83) wts[tid]=__ldg(kw2+(tid-34)*CC+c);

  for(int idx=tid;idx<3600;idx+=256){
    int ly=idx/60,lx=idx-ly*60;
    int gy=ty0-6+ly,gx=tx0-6+lx;
    float v=0.0f;
    if(gy>=0&&gy<HH&&gx>=0&&gx<WW) v=src[gy*WW+gx];
    buf0[idx]=v;
  }
  __syncthreads();

  for(int g=tid;g<58*15;g+=256){
    int oy=g/15,x0=(g-oy*15)*4;
    float o0=0.f,o1=0.f,o2=0.f,o3=0.f;
#pragma unroll
    for(int i=0;i<3;i++){
      const float* r=&buf0[(oy+i)*60+x0];
      float4 p=*(const float4*)r,q=*(const float4*)(r+4);
      float w0=wts[i*3],w1=wts[i*3+1],w2=wts[i*3+2];
      o0=fmaf(p.x,w0,o0);o0=fmaf(p.y,w1,o0);o0=fmaf(p.z,w2,o0);
      o1=fmaf(p.y,w0,o1);o1=fmaf(p.z,w1,o1);o1=fmaf(p.w,w2,o1);
      o2=fmaf(p.z,w0,o2);o2=fmaf(p.w,w1,o2);o2=fmaf(q.x,w2,o2);
      o3=fmaf(p.w,w0,o3);o3=fmaf(q.x,w1,o3);o3=fmaf(q.y,w2,o3);
    }
    int gy=ty0-5+oy,gxb=tx0-5+x0;
    bool iny=(gy>=0)&(gy<HH);
    float* dst=&buf1[oy*60+x0];
    dst[0]=(iny&(gxb>=0)&(gxb<WW))?gelu_exact(o0):0.f;
    dst[1]=(iny&(gxb+1>=0)&(gxb+1<WW))?gelu_exact(o1):0.f;
    dst[2]=(iny&(gxb+2>=0)&(gxb+2<WW))?gelu_exact(o2):0.f;
    dst[3]=(iny&(gxb+3>=0)&(gxb+3<WW))?gelu_exact(o3):0.f;
  }
  __syncthreads();

  for(int g=tid;g<54*14;g+=256){
    int oy=g/14,x0=(g-oy*14)*4;
    float o0=0.f,o1=0.f,o2=0.f,o3=0.f;
#pragma unroll
    for(int i=0;i<5;i++){
      const float* r=&buf1[(oy+i)*60+x0];
      float4 p=*(const float4*)r,q=*(const float4*)(r+4);
      float f[8]={p.x,p.y,p.z,p.w,q.x,q.y,q.z,q.w};
#pragma unroll
      for(int j=0;j<5;j++){
        float w=wts[9+i*5+j];
        o0=fmaf(f[j],w,o0); o1=fmaf(f[j+1],w,o1);
        o2=fmaf(f[j+2],w,o2); o3=fmaf(f[j+3],w,o3);
      }
    }
    int gy=ty0-3+oy,gxb=tx0-3+x0;
    bool iny=(gy>=0)&(gy<HH);
    float* dst=&buf2[oy*56+x0];
    dst[0]=(iny&(gxb>=0)&(gxb<WW))?gelu_exact(o0):0.f;
    dst[1]=(iny&(gxb+1>=0)&(gxb+1<WW))?gelu_exact(o1):0.f;
    dst[2]=(iny&(gxb+2>=0)&(gxb+2<WW))?gelu_exact(o2):0.f;
    dst[3]=(iny&(gxb+3>=0)&(gxb+3<WW))?gelu_exact(o3):0.f;
  }
  __syncthreads();

  float psum=0.0f;
  for(int g=tid;g<48*12;g+=256){
    int oy=g/12,x0=(g-oy*12)*4;
    float o0=0.f,o1=0.f,o2=0.f,o3=0.f;
#pragma unroll
    for(int i=0;i<7;i++){
      const float* r=&buf2[(oy+i)*56+x0];
      float4 p=*(const float4*)r,q=*(const float4*)(r+4),s4=*(const float4*)(r+8);
      float f[12]={p.x,p.y,p.z,p.w,q.x,q.y,q.z,q.w,s4.x,s4.y,s4.z,s4.w};
#pragma unroll
      for(int j=0;j<7;j++){
        float w=wts[34+i*7+j];
        o0=fmaf(f[j],w,o0); o1=fmaf(f[j+1],w,o1);
        o2=fmaf(f[j+2],w,o2); o3=fmaf(f[j+3],w,o3);
      }
    }
    float oo[4]={o0,o1,o2,o3};
    int gy=ty0+oy;
    float* dstall=g_ctxall+(size_t)(b*CC+c)*HWSZ+gy*WW;
#pragma unroll
    for(int d=0;d<4;d++){
      float c3=gelu_exact(oo[d]);
      psum+=c3;
      int gx=tx0+x0+d,n=b*HWSZ+gy*WW+gx;
      float4 gg=*(const float4*)(g_gates+(size_t)n*4);
      dstall[gx]=buf1[(oy+5)*60+(x0+d+5)]*gg.x+buf2[(oy+3)*56+(x0+d+3)]*gg.y+c3*gg.z;
    }
  }
#pragma unroll
  for(int off=16;off;off>>=1) psum+=__shfl_xor_sync(0xffffffffu,psum,off);
  if(lane==0) red8[warp]=psum;
  __syncthreads();
  if(tid<8){
    float s=red8[tid];
    s+=__shfl_xor_sync(0xffu,s,4);
    s+=__shfl_xor_sync(0xffu,s,2);
    s+=__shfl_xor_sync(0xffu,s,1);
    if(tid==0) atomicAdd(&g_pool[b*CC+c],s);
  }
}

__global__ void poolm_kernel(){
  g_cg[blockIdx.x*CC+threadIdx.x]=gelu_exact(g_pool[blockIdx.x*CC+threadIdx.x]*(1.0f/(float)HWSZ));
}

// ============ GEMM2 (bf16 2-split): modulator + q-mult + LayerNorm.
// A staged [k-pair][m] (src is k-major NCHW), B staged [k-pair][n].
__global__ __launch_bounds__(256) void gemm2_kernel(
  const float* __restrict__ Wh,const float* __restrict__ bh,
  const float* __restrict__ gamma,const float* __restrict__ beta)
{
  __shared__ uint32_t AsH[8*BP],AsL[8*BP],BsH[8*BP],BsL[8*BP];
  __shared__ float sg3[128],scg[128];
  __shared__ float redS[128][8],redQ[128][8];
  __shared__ float smu[128],srs[128];
  const int tid=threadIdx.x,lane=tid&31,w=tid>>5;
  const int wm=(w&3)*32,wn=(w>>2)*64,gid=lane>>2,tig=lane&3;
  const int row0=blockIdx.x*128,b=row0/HWSZ,p0=row0%HWSZ;

  if(tid<128){ sg3[tid]=g_gates[(size_t)(row0+tid)*4+3]; scg[tid]=g_cg[b*CC+tid]; }
  __syncthreads();

  float acc[2][8][4];
#pragma unroll
  for(int mi=0;mi<2;mi++)
#pragma unroll
    for(int ni=0;ni<8;ni++)
#pragma unroll
      for(int r=0;r<4;r++) acc[mi][ni][r]=0.0f;

  const int kp0=tid>>5, q0=(tid&31)*4;   // k-pair, m/n quad

  float4 pA0,pA1,pB0,pB1;
  pA0=*(const float4*)(g_ctxall+(size_t)(b*CC+2*kp0)*HWSZ+p0+q0);
  pA1=*(const float4*)(g_ctxall+(size_t)(b*CC+2*kp0+1)*HWSZ+p0+q0);
  pB0=*(const float4*)(Wh+(size_t)(2*kp0)*CC+q0);
  pB1=*(const float4*)(Wh+(size_t)(2*kp0+1)*CC+q0);

  for(int kc=0;kc<128;kc+=16){
    {
      float cg0=scg[kc+2*kp0],cg1=scg[kc+2*kp0+1];
      float a0x=pA0.x+sg3[q0]*cg0,   a0y=pA0.y+sg3[q0+1]*cg0;
      float a0z=pA0.z+sg3[q0+2]*cg0, a0w=pA0.w+sg3[q0+3]*cg0;
      float a1x=pA1.x+sg3[q0]*cg1,   a1y=pA1.y+sg3[q0+1]*cg1;
      float a1z=pA1.z+sg3[q0+2]*cg1, a1w=pA1.w+sg3[q0+3]*cg1;
      uint32_t h[4],l[4];
      bpack(a0x,a1x,&h[0],&l[0]); bpack(a0y,a1y,&h[1],&l[1]);
      bpack(a0z,a1z,&h[2],&l[2]); bpack(a0w,a1w,&h[3],&l[3]);
      *(uint4*)&AsH[kp0*BP+q0]=make_uint4(h[0],h[1],h[2],h[3]);
      *(uint4*)&AsL[kp0*BP+q0]=make_uint4(l[0],l[1],l[2],l[3]);
      bpack(pB0.x,pB1.x,&h[0],&l[0]); bpack(pB0.y,pB1.y,&h[1],&l[1]);
      bpack(pB0.z,pB1.z,&h[2],&l[2]); bpack(pB0.w,pB1.w,&h[3],&l[3]);
      *(uint4*)&BsH[kp0*BP+q0]=make_uint4(h[0],h[1],h[2],h[3]);
      *(uint4*)&BsL[kp0*BP+q0]=make_uint4(l[0],l[1],l[2],l[3]);
    }
    __syncthreads();
    if(kc<112){
      pA0=*(const float4*)(g_ctxall+(size_t)(b*CC+kc+16+2*kp0)*HWSZ+p0+q0);
      pA1=*(const float4*)(g_ctxall+(size_t)(b*CC+kc+16+2*kp0+1)*HWSZ+p0+q0);
      pB0=*(const float4*)(Wh+(size_t)(kc+16+2*kp0)*CC+q0);
      pB1=*(const float4*)(Wh+(size_t)(kc+16+2*kp0+1)*CC+q0);
    }
    uint32_t aH[2][4],aL[2][4];
#pragma unroll
    for(int mi=0;mi<2;mi++){
      int m0=wm+mi*16+gid;
      aH[mi][0]=AsH[tig*BP+m0];     aH[mi][1]=AsH[tig*BP+m0+8];
      aH[mi][2]=AsH[(tig+4)*BP+m0]; aH[mi][3]=AsH[(tig+4)*BP+m0+8];
      aL[mi][0]=AsL[tig*BP+m0];     aL[mi][1]=AsL[tig*BP+m0+8];
      aL[mi][2]=AsL[(tig+4)*BP+m0]; aL[mi][3]=AsL[(tig+4)*BP+m0+8];
    }
#pragma unroll
    for(int ni=0;ni<8;ni++){
      int nc=wn+ni*8+gid;
      uint32_t bH0=BsH[tig*BP+nc],bH1=BsH[(tig+4)*BP+nc];
      uint32_t bL0=BsL[tig*BP+nc],bL1=BsL[(tig+4)*BP+nc];
#pragma unroll
      for(int mi=0;mi<2;mi++){
        mma16(acc[mi][ni],aH[mi][0],aH[mi][1],aH[mi][2],aH[mi][3],bH0,bH1);
        mma16(acc[mi][ni],aH[mi][0],aH[mi][1],aH[mi][2],aH[mi][3],bL0,bL1);
        mma16(acc[mi][ni],aL[mi][0],aL[mi][1],aL[mi][2],aL[mi][3],bH0,bH1);
      }
    }
    __syncthreads();
  }

  float ps4[4]={0.f,0.f,0.f,0.f},pq4[4]={0.f,0.f,0.f,0.f};
#pragma unroll
  for(int mi=0;mi<2;mi++){
    int r0=row0+wm+mi*16+gid;
#pragma unroll
    for(int ni=0;ni<8;ni++){
      int cc2=wn+ni*8+2*tig;
      float bh0=__ldg(bh+cc2),bh1=__ldg(bh+cc2+1);
      float2 q0v=*(const float2*)(g_q+(size_t)r0*CC+cc2);
      float2 q1v=*(const float2*)(g_q+(size_t)(r0+8)*CC+cc2);
      float v0=q0v.x*(acc[mi][ni][0]+bh0),v1=q0v.y*(acc[mi][ni][1]+bh1);
      float v2=q1v.x*(acc[mi][ni][2]+bh0),v3=q1v.y*(acc[mi][ni][3]+bh1);
      acc[mi][ni][0]=v0; acc[mi][ni][1]=v1; acc[mi][ni][2]=v2; acc[mi][ni][3]=v3;
      ps4[mi*2]+=v0+v1; pq4[mi*2]=fmaf(v0,v0,fmaf(v1,v1,pq4[mi*2]));
      ps4[mi*2+1]+=v2+v3; pq4[mi*2+1]=fmaf(v2,v2,fmaf(v3,v3,pq4[mi*2+1]));
    }
  }
  const int col8=(w>>2)*4+tig;
#pragma unroll
  for(int mi=0;mi<2;mi++){
    int rl=wm+mi*16+gid;
    redS[rl][col8]=ps4[mi*2];     redQ[rl][col8]=pq4[mi*2];
    redS[rl+8][col8]=ps4[mi*2+1]; redQ[rl+8][col8]=pq4[mi*2+1];
  }
  __syncthreads();
  if(tid<128){
    float s=0.f,sq=0.f;
#pragma unroll
    for(int t=0;t<8;t++){ s+=redS[tid][t]; sq+=redQ[tid][t]; }
    float mu=s*(1.0f/CC),var=sq*(1.0f/CC)-mu*mu;
    smu[tid]=mu; srs[tid]=rsqrtf(var+LN_EPS);
  }
  __syncthreads();
#pragma unroll
  for(int mi=0;mi<2;mi++){
    int rl=wm+mi*16+gid,r0=row0+rl;
    float mu0=smu[rl],rs0=srs[rl],mu1=smu[rl+8],rs1=srs[rl+8];
#pragma unroll
    for(int ni=0;ni<8;ni++){
      int cc2=wn+ni*8+2*tig;
      float gm0=__ldg(gamma+cc2),gm1=__ldg(gamma+cc2+1);
      float be0=__ldg(beta+cc2),be1=__ldg(beta+cc2+1);
      *(float2*)(g_xout+(size_t)r0*CC+cc2)=make_float2(
        fmaf((acc[mi][ni][0]-mu0)*rs0,gm0,be0),fmaf((acc[mi][ni][1]-mu0)*rs0,gm1,be1));
      *(float2*)(g_xout+(size_t)(r0+8)*CC+cc2)=make_float2(
        fmaf((acc[mi][ni][2]-mu1)*rs1,gm0,be0),fmaf((acc[mi][ni][3]-mu1)*rs1,gm1,be1));
    }
  }
}

// ---------------- launcher ---------------------------------------------------
extern "C" void kernel_launch(void* const* d_in,const int* in_sizes,int n_in,
                              void* d_out,int out_size)
{
  const float *x=0,*Wf=0,*bf=0,*Wh=0,*bh=0,*gamma=0,*beta=0,*Wp=0,*bp=0,*k0=0,*k1=0,*k2=0;
  int n16384=0,n128=0;
  for(int i=0;i<n_in;i++){
    const float* p=(const float*)d_in[i];
    switch(in_sizes[i]){
      case 18874368: x=p; break;
      case 33280:    Wf=p; break;
      case 260:      bf=p; break;
      case 16384:    if(n16384++==0) Wh=p; else Wp=p; break;
      case 128:
        if(n128==0) bh=p; else if(n128==1) gamma=p;
        else if(n128==2) beta=p; else bp=p;
        n128++; break;
      case 1152: k0=p; break;
      case 3200: k1=p; break;
      case 6272: k2=p; break;
      default: break;
    }
  }
  float* out=(float*)d_out;

  zero_pool_kernel<<<8,256>>>();
  gemmA_kernel<<<dim3(2,NPIX/128),256>>>(x,Wf,260,bf,0,1);               // GEMM1: q + ctx + gates
  conv_kernel<<<dim3(4,CC,BB),256>>>(k0,k1,k2);
  poolm_kernel<<<BB,CC>>>();
  gemm2_kernel<<<NPIX/128,256>>>(Wh,bh,gamma,beta);
  gemmA_kernel<<<dim3(1,NPIX/128),256>>>((const float*)0,Wp,CC,bp,out,0); // GEMM3
  (void)out_size;
}